// round 6
// baseline (speedup 1.0000x reference)
#include <cuda_runtime.h>
#include <cuda_bf16.h>

// LinearSpline activation, division-free, channel-folded:
//   t  = x * (s[c]*6.25f)                 (6.25f == float(1/0.16), exact)
//   tc = clamp(t, -25.0f, 24.0f)          (== reference clip-then-divide)
//   ip = (int)floor(tc);  fr = t - ip     (fr from unclamped t, per reference)
//   out = fma(fr, C1-C0, C0)   where (C0,C1) = (c[z+ip]/s, c[z+ip+1]/s)
//
// R6 = R4 (best ncu, no cache hints) + R5's lean folded chain + 40 warps/SM.
// Cache hints (__ldcs/__stcs) are excluded: R3/R5 show they cost ~8-10 DRAM
// points on this part regardless of warp/ILP shape.
// Gather table: 12-byte cells (C0, C1, pad); bank = (3*idx)%32, gcd(3,32)=1
// -> conflict-free for the Gaussian-concentrated idx window.

#define NUM_ACT 64
#define SIZE    51
#define TABLE   (NUM_ACT * SIZE)   // 3264

__global__ __launch_bounds__(256, 5)
void linear_spline_kernel(const float4* __restrict__ x,
                          const float*  __restrict__ coef,
                          const float*  __restrict__ scale,
                          float4*       __restrict__ out,
                          int n4)
{
    __shared__ float sc3[TABLE * 3];    // (c0/s, c1/s, pad) cells, 39 KB
    __shared__ float s625[NUM_ACT];     // s[c] * 6.25f

    for (int i = threadIdx.x; i < TABLE; i += 256) {
        int   c  = i / SIZE;
        float rs = 1.0f / scale[c];                      // exact for s==1
        float a  = coef[i] * rs;
        float b  = (i + 1 < TABLE) ? coef[i + 1] * rs : 0.0f;  // edge never used
        sc3[3 * i]     = a;
        sc3[3 * i + 1] = b;
    }
    if (threadIdx.x < NUM_ACT) {
        s625[threadIdx.x] = scale[threadIdx.x] * 6.25f;  // exact for s==1
    }
    __syncthreads();

    const int stride = gridDim.x * blockDim.x;
    int i = blockIdx.x * blockDim.x + threadIdx.x;

    // ~10 warp-ops + 2 conflict-free LDS.32 per element; index chain is
    // t -> clamp -> F2I.RD (one 20-cyc convert before the LDS address).
    #define ELEM(v, ov, zk3_, sg_) {                     \
        float t  = (v) * (sg_);                          \
        float tc = fminf(fmaxf(t, -25.0f), 24.0f);       \
        int   ip = __float2int_rd(tc);                   \
        float fr = t - (float)ip;                        \
        int p = (zk3_) + 3 * ip;                         \
        float c0 = sc3[p];                               \
        float c1 = sc3[p + 1];                           \
        (ov) = fmaf(fr, c1 - c0, c0); }

    // ILP=4: four independent LDG.128 in flight before any dependent compute.
    for (; i + 3 * stride < n4; i += 4 * stride) {
        float4 xv[4];
        #pragma unroll
        for (int u = 0; u < 4; u++) xv[u] = x[i + u * stride];

        #pragma unroll
        for (int u = 0; u < 4; u++) {
            const int j = i + u * stride;
            const int c = (j >> 12) & (NUM_ACT - 1);    // 4096 float4 per channel
            const float sg = s625[c];
            const int zk3 = c * (SIZE * 3) + (SIZE / 2) * 3;
            float4 o;
            ELEM(xv[u].x, o.x, zk3, sg)
            ELEM(xv[u].y, o.y, zk3, sg)
            ELEM(xv[u].z, o.z, zk3, sg)
            ELEM(xv[u].w, o.w, zk3, sg)
            out[j] = o;
        }
    }
    // tail: up to 3 more trips per thread
    for (; i < n4; i += stride) {
        float4 xv = x[i];
        const int c = (i >> 12) & (NUM_ACT - 1);
        const float sg = s625[c];
        const int zk3 = c * (SIZE * 3) + (SIZE / 2) * 3;
        float4 o;
        ELEM(xv.x, o.x, zk3, sg)
        ELEM(xv.y, o.y, zk3, sg)
        ELEM(xv.z, o.z, zk3, sg)
        ELEM(xv.w, o.w, zk3, sg)
        out[i] = o;
    }
    #undef ELEM
}

extern "C" void kernel_launch(void* const* d_in, const int* in_sizes, int n_in,
                              void* d_out, int out_size)
{
    const float* x     = (const float*)d_in[0];
    const float* coef  = (const float*)d_in[1];
    const float* scale = (const float*)d_in[2];
    float* out         = (float*)d_out;

    const int n  = in_sizes[0];   // 33,554,432
    const int n4 = n / 4;         // 8,388,608

    const int threads = 256;
    const int blocks  = 148 * 5;  // 5 CTAs/SM = 40 warps, ILP=4, no cache hints

    linear_spline_kernel<<<blocks, threads>>>(
        (const float4*)x, coef, scale, (float4*)out, n4);
}

// round 7
// speedup vs baseline: 1.1709x; 1.1709x over previous
#include <cuda_runtime.h>
#include <cuda_bf16.h>

// LinearSpline activation, division-free, channel-folded:
//   t  = x * (s[c]*6.25f)                 (6.25f == float(1/0.16), exact)
//   tc = clamp(t, -25.0f, 24.0f)          (== reference clip-then-divide)
//   ip = (int)floor(tc);  fr = t - ip     (fr from unclamped t, per reference)
//   out = fma(fr, C1-C0, C0)   where (C0,C1) = (c[z+ip]/s, c[z+ip+1]/s)
//
// R7 combines the three independently-verified winners:
//  - stride-3 conflict-free gather table (12B cells, bank=(3*idx)%32)
//  - 48 warps/SM x ILP2 = 96 in-flight LDG.128 units (the R2/R4 plateau)
//  - LARGE L1: 3 CTAs x 512 thr -> smem carveout 117KB, ~111KB L1 left.
//    (Rounds with <=33KB L1 all regressed to ~51-53% DRAM; >=68KB hit ~61%.)

#define NUM_ACT 64
#define SIZE    51
#define TABLE   (NUM_ACT * SIZE)   // 3264

__global__ __launch_bounds__(512, 3)
void linear_spline_kernel(const float4* __restrict__ x,
                          const float*  __restrict__ coef,
                          const float*  __restrict__ scale,
                          float4*       __restrict__ out,
                          int n4)
{
    __shared__ float sc3[TABLE * 3];    // (c0/s, c1/s, pad) cells, 39 KB
    __shared__ float s625[NUM_ACT];     // s[c] * 6.25f

    for (int i = threadIdx.x; i < TABLE; i += 512) {
        int   c  = i / SIZE;
        float rs = 1.0f / scale[c];                      // exact for s==1
        float a  = coef[i] * rs;
        float b  = (i + 1 < TABLE) ? coef[i + 1] * rs : 0.0f;  // edge never used
        sc3[3 * i]     = a;
        sc3[3 * i + 1] = b;
    }
    if (threadIdx.x < NUM_ACT) {
        s625[threadIdx.x] = scale[threadIdx.x] * 6.25f;  // exact for s==1
    }
    __syncthreads();

    const int stride = gridDim.x * blockDim.x;
    int i = blockIdx.x * blockDim.x + threadIdx.x;

    // ~10 warp-ops + 2 conflict-free LDS.32 per element.
    #define ELEM(v, ov, zk3_, sg_) {                     \
        float t  = (v) * (sg_);                          \
        float tc = fminf(fmaxf(t, -25.0f), 24.0f);       \
        int   ip = __float2int_rd(tc);                   \
        float fr = t - (float)ip;                        \
        int p = (zk3_) + 3 * ip;                         \
        float c0 = sc3[p];                               \
        float c1 = sc3[p + 1];                           \
        (ov) = fmaf(fr, c1 - c0, c0); }

    // ILP=2: two independent LDG.128 in flight before any dependent compute.
    for (; i + stride < n4; i += 2 * stride) {
        const int j = i + stride;
        float4 xa = x[i];
        float4 xb = x[j];

        const int ca = (i >> 12) & (NUM_ACT - 1);   // 4096 float4 per channel
        const int cb = (j >> 12) & (NUM_ACT - 1);
        const float sga = s625[ca];
        const float sgb = s625[cb];
        const int zka3 = ca * (SIZE * 3) + (SIZE / 2) * 3;
        const int zkb3 = cb * (SIZE * 3) + (SIZE / 2) * 3;

        float4 oa, ob;
        ELEM(xa.x, oa.x, zka3, sga)
        ELEM(xa.y, oa.y, zka3, sga)
        ELEM(xa.z, oa.z, zka3, sga)
        ELEM(xa.w, oa.w, zka3, sga)
        ELEM(xb.x, ob.x, zkb3, sgb)
        ELEM(xb.y, ob.y, zkb3, sgb)
        ELEM(xb.z, ob.z, zkb3, sgb)
        ELEM(xb.w, ob.w, zkb3, sgb)

        out[i] = oa;
        out[j] = ob;
    }
    // tail
    if (i < n4) {
        float4 xv = x[i];
        const int c = (i >> 12) & (NUM_ACT - 1);
        const float sg = s625[c];
        const int zk3 = c * (SIZE * 3) + (SIZE / 2) * 3;
        float4 o;
        ELEM(xv.x, o.x, zk3, sg)
        ELEM(xv.y, o.y, zk3, sg)
        ELEM(xv.z, o.z, zk3, sg)
        ELEM(xv.w, o.w, zk3, sg)
        out[i] = o;
    }
    #undef ELEM
}

extern "C" void kernel_launch(void* const* d_in, const int* in_sizes, int n_in,
                              void* d_out, int out_size)
{
    const float* x     = (const float*)d_in[0];
    const float* coef  = (const float*)d_in[1];
    const float* scale = (const float*)d_in[2];
    float* out         = (float*)d_out;

    const int n  = in_sizes[0];   // 33,554,432
    const int n4 = n / 4;         // 8,388,608

    const int threads = 512;
    const int blocks  = 148 * 3;  // 3 CTAs/SM = 48 warps, smem 117KB, L1 ~111KB

    linear_spline_kernel<<<blocks, threads>>>(
        (const float4*)x, coef, scale, (float4*)out, n4);
}

// round 8
// speedup vs baseline: 1.1811x; 1.0087x over previous
#include <cuda_runtime.h>
#include <cuda_bf16.h>

// LinearSpline activation, division-free, channel-folded:
//   t  = x * (s[c]*6.25f)                 (6.25f == float(1/0.16), exact)
//   tc = clamp(t, -25.0f, 24.0f)          (== reference clip-then-divide)
//   ip = (int)floor(tc);  fr = t - ip     (fr from unclamped t, per reference)
//   out = fma(fr, C1-C0, C0)   where (C0,C1) = (c[z+ip]/s, c[z+ip+1]/s)
//
// R8 = R7 with the L1 carveout pushed further: 2 CTAs x 768 threads
// (48 warps/SM unchanged, ILP2 unchanged) -> smem 78KB, L1 left ~150KB.
// Dose-response so far (L1-left vs DRAM%): 33KB->51-53, 68KB->61-62,
// 111KB->63.3. Testing 150KB isolates whether the L1 fill-resource axis
// has saturated.
// Gather table: 12-byte cells (C0, C1, pad); bank=(3*idx)%32, gcd(3,32)=1
// -> conflict-free for the Gaussian-concentrated idx window.

#define NUM_ACT 64
#define SIZE    51
#define TABLE   (NUM_ACT * SIZE)   // 3264

__global__ __launch_bounds__(768, 2)
void linear_spline_kernel(const float4* __restrict__ x,
                          const float*  __restrict__ coef,
                          const float*  __restrict__ scale,
                          float4*       __restrict__ out,
                          int n4)
{
    __shared__ float sc3[TABLE * 3];    // (c0/s, c1/s, pad) cells, 39 KB
    __shared__ float s625[NUM_ACT];     // s[c] * 6.25f

    for (int i = threadIdx.x; i < TABLE; i += 768) {
        int   c  = i / SIZE;
        float rs = 1.0f / scale[c];                      // exact for s==1
        float a  = coef[i] * rs;
        float b  = (i + 1 < TABLE) ? coef[i + 1] * rs : 0.0f;  // edge never used
        sc3[3 * i]     = a;
        sc3[3 * i + 1] = b;
    }
    if (threadIdx.x < NUM_ACT) {
        s625[threadIdx.x] = scale[threadIdx.x] * 6.25f;  // exact for s==1
    }
    __syncthreads();

    const int stride = gridDim.x * blockDim.x;
    int i = blockIdx.x * blockDim.x + threadIdx.x;

    // ~10 warp-ops + 2 conflict-free LDS.32 per element.
    #define ELEM(v, ov, zk3_, sg_) {                     \
        float t  = (v) * (sg_);                          \
        float tc = fminf(fmaxf(t, -25.0f), 24.0f);       \
        int   ip = __float2int_rd(tc);                   \
        float fr = t - (float)ip;                        \
        int p = (zk3_) + 3 * ip;                         \
        float c0 = sc3[p];                               \
        float c1 = sc3[p + 1];                           \
        (ov) = fmaf(fr, c1 - c0, c0); }

    // ILP=2: two independent LDG.128 in flight before any dependent compute.
    for (; i + stride < n4; i += 2 * stride) {
        const int j = i + stride;
        float4 xa = x[i];
        float4 xb = x[j];

        const int ca = (i >> 12) & (NUM_ACT - 1);   // 4096 float4 per channel
        const int cb = (j >> 12) & (NUM_ACT - 1);
        const float sga = s625[ca];
        const float sgb = s625[cb];
        const int zka3 = ca * (SIZE * 3) + (SIZE / 2) * 3;
        const int zkb3 = cb * (SIZE * 3) + (SIZE / 2) * 3;

        float4 oa, ob;
        ELEM(xa.x, oa.x, zka3, sga)
        ELEM(xa.y, oa.y, zka3, sga)
        ELEM(xa.z, oa.z, zka3, sga)
        ELEM(xa.w, oa.w, zka3, sga)
        ELEM(xb.x, ob.x, zkb3, sgb)
        ELEM(xb.y, ob.y, zkb3, sgb)
        ELEM(xb.z, ob.z, zkb3, sgb)
        ELEM(xb.w, ob.w, zkb3, sgb)

        out[i] = oa;
        out[j] = ob;
    }
    // tail
    if (i < n4) {
        float4 xv = x[i];
        const int c = (i >> 12) & (NUM_ACT - 1);
        const float sg = s625[c];
        const int zk3 = c * (SIZE * 3) + (SIZE / 2) * 3;
        float4 o;
        ELEM(xv.x, o.x, zk3, sg)
        ELEM(xv.y, o.y, zk3, sg)
        ELEM(xv.z, o.z, zk3, sg)
        ELEM(xv.w, o.w, zk3, sg)
        out[i] = o;
    }
    #undef ELEM
}

extern "C" void kernel_launch(void* const* d_in, const int* in_sizes, int n_in,
                              void* d_out, int out_size)
{
    const float* x     = (const float*)d_in[0];
    const float* coef  = (const float*)d_in[1];
    const float* scale = (const float*)d_in[2];
    float* out         = (float*)d_out;

    const int n  = in_sizes[0];   // 33,554,432
    const int n4 = n / 4;         // 8,388,608

    const int threads = 768;
    const int blocks  = 148 * 2;  // 2 CTAs/SM = 48 warps, smem 78KB, L1 ~150KB

    linear_spline_kernel<<<blocks, threads>>>(
        (const float4*)x, coef, scale, (float4*)out, n4);
}

// round 9
// speedup vs baseline: 1.2169x; 1.0302x over previous
#include <cuda_runtime.h>
#include <cuda_bf16.h>

// LinearSpline activation, division-free, channel-folded:
//   t  = x * (s[c]*6.25f)                 (6.25f == float(1/0.16), exact)
//   tc = clamp(t, -25.0f, 24.0f)          (== reference clip-then-divide)
//   ip = (int)floor(tc);  fr = t - ip     (fr from unclamped t, per reference)
//   out = fma(fr, C1-C0, C0)   where (C0,C1) = (c[z+ip]/s, c[z+ip+1]/s)
//
// R9 = R8 with a minimal smem footprint to maximize the L1 carveout:
// plain float[3264] table (13.3KB) gathered with two LDS.32 at idx, idx+1.
// smem/SM drops 78KB -> ~27KB, leaving ~200KB L1. Dose-response so far
// (L1-left vs DRAM%): 33->52, 68->61.5, 111->63.3, 150->66.5 — not saturated.
// Bank model: bank = idx%32, warp idx Gaussian(25,6.25) in [0,50] -> only
// tail pairs (k, k+32) collide; expected conflict degree ~1.2-1.5.

#define NUM_ACT 64
#define SIZE    51
#define TABLE   (NUM_ACT * SIZE)   // 3264

__global__ __launch_bounds__(768, 2)
void linear_spline_kernel(const float4* __restrict__ x,
                          const float*  __restrict__ coef,
                          const float*  __restrict__ scale,
                          float4*       __restrict__ out,
                          int n4)
{
    __shared__ float sc[TABLE];         // c[i]/s[c], 13.3 KB
    __shared__ float s625[NUM_ACT];     // s[c] * 6.25f

    for (int i = threadIdx.x; i < TABLE; i += 768) {
        int   c  = i / SIZE;
        float rs = 1.0f / scale[c];                      // exact for s==1
        sc[i] = coef[i] * rs;
    }
    if (threadIdx.x < NUM_ACT) {
        s625[threadIdx.x] = scale[threadIdx.x] * 6.25f;  // exact for s==1
    }
    __syncthreads();

    const int stride = gridDim.x * blockDim.x;
    int i = blockIdx.x * blockDim.x + threadIdx.x;

    // ~10 warp-ops + 2 LDS.32 per element. Max idx = 63*51+49+1 = 3263: in-bounds.
    #define ELEM(v, ov, zk_, sg_) {                      \
        float t  = (v) * (sg_);                          \
        float tc = fminf(fmaxf(t, -25.0f), 24.0f);       \
        int   ip = __float2int_rd(tc);                   \
        float fr = t - (float)ip;                        \
        int p = (zk_) + ip;                              \
        float c0 = sc[p];                                \
        float c1 = sc[p + 1];                            \
        (ov) = fmaf(fr, c1 - c0, c0); }

    // ILP=2: two independent LDG.128 in flight before any dependent compute.
    for (; i + stride < n4; i += 2 * stride) {
        const int j = i + stride;
        float4 xa = x[i];
        float4 xb = x[j];

        const int ca = (i >> 12) & (NUM_ACT - 1);   // 4096 float4 per channel
        const int cb = (j >> 12) & (NUM_ACT - 1);
        const float sga = s625[ca];
        const float sgb = s625[cb];
        const int zka = ca * SIZE + SIZE / 2;
        const int zkb = cb * SIZE + SIZE / 2;

        float4 oa, ob;
        ELEM(xa.x, oa.x, zka, sga)
        ELEM(xa.y, oa.y, zka, sga)
        ELEM(xa.z, oa.z, zka, sga)
        ELEM(xa.w, oa.w, zka, sga)
        ELEM(xb.x, ob.x, zkb, sgb)
        ELEM(xb.y, ob.y, zkb, sgb)
        ELEM(xb.z, ob.z, zkb, sgb)
        ELEM(xb.w, ob.w, zkb, sgb)

        out[i] = oa;
        out[j] = ob;
    }
    // tail
    if (i < n4) {
        float4 xv = x[i];
        const int c = (i >> 12) & (NUM_ACT - 1);
        const float sg = s625[c];
        const int zk = c * SIZE + SIZE / 2;
        float4 o;
        ELEM(xv.x, o.x, zk, sg)
        ELEM(xv.y, o.y, zk, sg)
        ELEM(xv.z, o.z, zk, sg)
        ELEM(xv.w, o.w, zk, sg)
        out[i] = o;
    }
    #undef ELEM
}

extern "C" void kernel_launch(void* const* d_in, const int* in_sizes, int n_in,
                              void* d_out, int out_size)
{
    const float* x     = (const float*)d_in[0];
    const float* coef  = (const float*)d_in[1];
    const float* scale = (const float*)d_in[2];
    float* out         = (float*)d_out;

    const int n  = in_sizes[0];   // 33,554,432
    const int n4 = n / 4;         // 8,388,608

    const int threads = 768;
    const int blocks  = 148 * 2;  // 2 CTAs/SM = 48 warps, smem ~27KB, L1 ~200KB

    linear_spline_kernel<<<blocks, threads>>>(
        (const float4*)x, coef, scale, (float4*)out, n4);
}